// round 10
// baseline (speedup 1.0000x reference)
#include <cuda_runtime.h>
#include <math.h>

// Problem constants
#define BB   4
#define HH   64
#define WW   64
#define MTOT (BB*HH*WW)      // 16384 pixels
#define CC   256             // coarse / fine channels
#define CF2  512             // concat channels
#define NOM  216             // G*3*K = 8*27
#define KIM  4608            // 9*512 im2col K
#define KDCN 2304            // 9*256
#define GRP  8
#define CG   32              // channels per group

// ---------------- packed f32x2 helpers (Blackwell) ---------------------------
__device__ __forceinline__ unsigned long long pack2(float lo, float hi) {
    unsigned long long r;
    asm("mov.b64 %0, {%1, %2};" : "=l"(r) : "f"(lo), "f"(hi));
    return r;
}
__device__ __forceinline__ void unpack2(unsigned long long v, float& lo, float& hi) {
    asm("mov.b64 {%0, %1}, %2;" : "=f"(lo), "=f"(hi) : "l"(v));
}
__device__ __forceinline__ void fma2(unsigned long long& d, unsigned long long a,
                                     unsigned long long b) {
    asm("fma.rn.f32x2 %0, %1, %2, %0;" : "+l"(d) : "l"(a), "l"(b));
}

// ---------------- scratch (static device globals; no allocation) -------------
__device__ float g_coarse_up[MTOT*CC];        // 16.8 MB
__device__ float g_pool_part[64*CC];
__device__ float g_attn_p1[BB*CC];            // 1 + sigmoid(attn)
__device__ float g_fine_cal[MTOT*CC];         // 16.8 MB
__device__ float g_align[MTOT*CF2];           // 33.6 MB
__device__ float g_om[MTOT*NOM];              // 14.2 MB
__device__ float g_sampled[(size_t)MTOT*KDCN];// 151 MB

// ---------------- bilinear upsample (half-pixel, edge clamp) ------------------
__global__ void upsample_kernel(const float* __restrict__ coarse) {
    int idx = blockIdx.x * blockDim.x + threadIdx.x;   // [0, 4*64*64*64)
    if (idx >= BB*HH*WW*(CC/4)) return;
    int c4 = idx & 63;
    int x  = (idx >> 6) & 63;
    int y  = (idx >> 12) & 63;
    int b  = idx >> 18;

    float syf = y * 0.5f - 0.25f;
    float sxf = x * 0.5f - 0.25f;
    float y0f = floorf(syf), x0f = floorf(sxf);
    float wy = syf - y0f, wx = sxf - x0f;
    int y0 = max(0, min(31, (int)y0f));
    int y1 = max(0, min(31, (int)y0f + 1));
    int x0 = max(0, min(31, (int)x0f));
    int x1 = max(0, min(31, (int)x0f + 1));

    const float4* src = (const float4*)coarse;
    int base = ((b * 32) * 32) * 64;   // in float4 units per row plane
    float4 v00 = src[base + (y0 * 32 + x0) * 64 + c4];
    float4 v01 = src[base + (y0 * 32 + x1) * 64 + c4];
    float4 v10 = src[base + (y1 * 32 + x0) * 64 + c4];
    float4 v11 = src[base + (y1 * 32 + x1) * 64 + c4];

    float4 r;
    r.x = (v00.x*(1-wx)+v01.x*wx)*(1-wy) + (v10.x*(1-wx)+v11.x*wx)*wy;
    r.y = (v00.y*(1-wx)+v01.y*wx)*(1-wy) + (v10.y*(1-wx)+v11.y*wx)*wy;
    r.z = (v00.z*(1-wx)+v01.z*wx)*(1-wy) + (v10.z*(1-wx)+v11.z*wx)*wy;
    r.w = (v00.w*(1-wx)+v01.w*wx)*(1-wy) + (v10.w*(1-wx)+v11.w*wx)*wy;

    ((float4*)g_coarse_up)[((b*64 + y)*64 + x)*64 + c4] = r;
}

// ---------------- global mean pool: partial sums --------------------------------
__global__ void pool_part_kernel(const float* __restrict__ fine) {
    int bx = blockIdx.x;          // 64 blocks: b = bx>>4, spatial chunk = bx&15
    int b = bx >> 4, t = bx & 15;
    int c = threadIdx.x;
    float acc = 0.f;
    const float* p = fine + ((size_t)(b << 12) + t * 256) * CC + c;
    for (int s = 0; s < 256; s++) acc += p[(size_t)s * CC];
    g_pool_part[bx * CC + c] = acc;
}

// ---------------- attention: reduce partials, 1x1 conv, sigmoid+1 ----------------
__global__ void attn_kernel(const float* __restrict__ w_att) {
    __shared__ float ps[CC];
    int b = blockIdx.x, c = threadIdx.x;
    float acc = 0.f;
    for (int t = 0; t < 16; t++) acc += g_pool_part[(b * 16 + t) * CC + c];
    ps[c] = acc * (1.0f / 4096.0f);
    __syncthreads();
    float logit = 0.f;
    for (int k = 0; k < CC; k++) logit = fmaf(ps[k], w_att[k * CC + c], logit);
    g_attn_p1[b * CC + c] = 1.0f + 1.0f / (1.0f + expf(-logit));
}

// ---------------- generic tiled SGEMM with fused A-loaders / epilogues ----------
// AMODE: 0 plain A, 1 fine*(attn+1), 2 concat(fine_cal, 2*coarse_up), 3 im2col(align)
// EPI:   0 none, 1 +bias, 2 relu(+bias)+epi_add
// Double-buffered smem (1 sync/iter) + register prefetch of next global tile
// + fragment double-buffering over kk + packed f32x2 FMA (FFMA2) inner loop.
#define Bb 128
#define Bn 128
#define Bk 16

template<int AMODE>
__device__ __forceinline__ float loadA(const float* __restrict__ A,
                                       const float* __restrict__ aux0,
                                       const float* __restrict__ aux1,
                                       int m, int k, int K) {
    if (AMODE == 0) return A[(size_t)m * K + k];
    if (AMODE == 1) return aux0[m * CC + k] * aux1[((m >> 12) << 8) + k];
    if (AMODE == 2) return (k < CC) ? aux0[m * CC + k]
                                    : 2.0f * aux1[m * CC + (k - CC)];
    // AMODE == 3 : im2col over g_align [B,H,W,512], SAME zero pad
    {
        int r = k >> 9;            // 0..8  (tap)
        int c = k & 511;
        int ky = r / 3 - 1, kx = r % 3 - 1;
        int b = m >> 12, y = (m >> 6) & 63, x = m & 63;
        int yy = y + ky, xx = x + kx;
        if ((unsigned)yy < 64u && (unsigned)xx < 64u)
            return aux0[((((b << 6) + yy) << 6) + xx) * CF2 + c];
        return 0.f;
    }
}

template<int AMODE, int EPI>
__global__ void __launch_bounds__(256)
gemm_kernel(const float* __restrict__ A, const float* __restrict__ B,
            float* __restrict__ C, int M, int N, int K,
            const float* __restrict__ aux0, const float* __restrict__ aux1,
            const float* __restrict__ bias, const float* __restrict__ epi_add) {
    __shared__ float As[2][Bk][Bb + 4];
    __shared__ float Bs[2][Bk][Bn];

    int tid = threadIdx.x;
    int tx = tid & 15, ty = tid >> 4;
    int m0 = blockIdx.y * Bb;
    int n0 = blockIdx.x * Bn;

    // packed accumulators: acc2[i][j2] holds C[m0+ty*8+i][n0+tx*8+2*j2 (+1)]
    unsigned long long acc2[8][4];
#pragma unroll
    for (int i = 0; i < 8; i++)
#pragma unroll
        for (int j = 0; j < 4; j++) acc2[i][j] = 0ULL;

    int a_kk = tid & 15;          // A loader: fixed k lane per thread
    int a_mrow = tid >> 4;
    int b_nn = tid & 127;         // B loader: fixed n lane per thread
    int b_krow = tid >> 7;

    float pa[8], pb[8];           // global prefetch registers

    // ---- prologue: fetch tile 0 into buffer 0 ----
#pragma unroll
    for (int t = 0; t < 8; t++)
        pa[t] = loadA<AMODE>(A, aux0, aux1, m0 + a_mrow + t * 16, a_kk, K);
#pragma unroll
    for (int t = 0; t < 8; t++) {
        int n = n0 + b_nn;
        pb[t] = (n < N) ? B[(size_t)(b_krow + t * 2) * N + n] : 0.f;
    }
#pragma unroll
    for (int t = 0; t < 8; t++) As[0][a_kk][a_mrow + t * 16] = pa[t];
#pragma unroll
    for (int t = 0; t < 8; t++) Bs[0][b_krow + t * 2][b_nn] = pb[t];
    __syncthreads();

    int buf = 0;
    for (int k0 = 0; k0 < K; k0 += Bk, buf ^= 1) {
        bool has_next = (k0 + Bk) < K;
        // ---- issue next tile's global loads early ----
        if (has_next) {
            int kn = k0 + Bk;
#pragma unroll
            for (int t = 0; t < 8; t++)
                pa[t] = loadA<AMODE>(A, aux0, aux1, m0 + a_mrow + t * 16, kn + a_kk, K);
#pragma unroll
            for (int t = 0; t < 8; t++) {
                int n = n0 + b_nn;
                pb[t] = (n < N) ? B[(size_t)(kn + b_krow + t * 2) * N + n] : 0.f;
            }
        }

        // ---- compute on current buffer; fragments double-buffered over kk ----
        float rA[2][8];
        unsigned long long rB2[2][4];
        {
            float4 a0 = *(const float4*)&As[buf][0][ty * 8];
            float4 a1 = *(const float4*)&As[buf][0][ty * 8 + 4];
            float4 b0 = *(const float4*)&Bs[buf][0][tx * 8];
            float4 b1 = *(const float4*)&Bs[buf][0][tx * 8 + 4];
            rA[0][0]=a0.x; rA[0][1]=a0.y; rA[0][2]=a0.z; rA[0][3]=a0.w;
            rA[0][4]=a1.x; rA[0][5]=a1.y; rA[0][6]=a1.z; rA[0][7]=a1.w;
            rB2[0][0]=pack2(b0.x,b0.y); rB2[0][1]=pack2(b0.z,b0.w);
            rB2[0][2]=pack2(b1.x,b1.y); rB2[0][3]=pack2(b1.z,b1.w);
        }
#pragma unroll
        for (int kk = 0; kk < Bk; kk++) {
            int cur = kk & 1, nxt = cur ^ 1;
            if (kk < Bk - 1) {
                float4 a0 = *(const float4*)&As[buf][kk + 1][ty * 8];
                float4 a1 = *(const float4*)&As[buf][kk + 1][ty * 8 + 4];
                float4 b0 = *(const float4*)&Bs[buf][kk + 1][tx * 8];
                float4 b1 = *(const float4*)&Bs[buf][kk + 1][tx * 8 + 4];
                rA[nxt][0]=a0.x; rA[nxt][1]=a0.y; rA[nxt][2]=a0.z; rA[nxt][3]=a0.w;
                rA[nxt][4]=a1.x; rA[nxt][5]=a1.y; rA[nxt][6]=a1.z; rA[nxt][7]=a1.w;
                rB2[nxt][0]=pack2(b0.x,b0.y); rB2[nxt][1]=pack2(b0.z,b0.w);
                rB2[nxt][2]=pack2(b1.x,b1.y); rB2[nxt][3]=pack2(b1.z,b1.w);
            }
#pragma unroll
            for (int i = 0; i < 8; i++) {
                unsigned long long a2 = pack2(rA[cur][i], rA[cur][i]);
#pragma unroll
                for (int j = 0; j < 4; j++)
                    fma2(acc2[i][j], a2, rB2[cur][j]);
            }
        }

        // ---- store next tile into the other buffer; single barrier ----
        if (has_next) {
#pragma unroll
            for (int t = 0; t < 8; t++) As[buf ^ 1][a_kk][a_mrow + t * 16] = pa[t];
#pragma unroll
            for (int t = 0; t < 8; t++) Bs[buf ^ 1][b_krow + t * 2][b_nn] = pb[t];
            __syncthreads();
        }
    }

#pragma unroll
    for (int i = 0; i < 8; i++) {
        int m = m0 + ty * 8 + i;
#pragma unroll
        for (int j = 0; j < 4; j++) {
            float vlo, vhi;
            unpack2(acc2[i][j], vlo, vhi);
            int n = n0 + tx * 8 + j * 2;
#pragma unroll
            for (int h = 0; h < 2; h++) {
                int nn = n + h;
                if (nn < N) {
                    float v = (h == 0) ? vlo : vhi;
                    if (EPI == 1) v += bias[nn];
                    if (EPI == 2) v = fmaxf(v + bias[nn], 0.f) + epi_add[(size_t)m * N + nn];
                    C[(size_t)m * N + nn] = v;
                }
            }
        }
    }
}

// ---------------- deformable bilinear sampling ------------------------------------
// thread -> (m, k, g); writes 32 contiguous channels of g_sampled[m][k][g*32..]
__global__ void sample_kernel() {
    int idx = blockIdx.x * blockDim.x + threadIdx.x;   // [0, 16384*72)
    if (idx >= MTOT * 9 * GRP) return;
    int g  = idx & 7;
    int mk = idx >> 3;
    int k  = mk % 9;
    int m  = mk / 9;
    int b = m >> 12, y = (m >> 6) & 63, x = m & 63;

    const float* omp = g_om + (size_t)m * NOM;
    float dy = omp[g * 18 + k * 2];
    float dx = omp[g * 18 + k * 2 + 1];
    float mask = 1.0f / (1.0f + expf(-omp[144 + g * 9 + k]));

    float sy = (float)y + (float)(k / 3 - 1) + dy;
    float sx = (float)x + (float)(k % 3 - 1) + dx;
    float y0f = floorf(sy), x0f = floorf(sx);
    float wy = sy - y0f, wx = sx - x0f;

    float vy0 = (y0f >= 0.f && y0f <= 63.f) ? 1.f : 0.f;
    float vy1 = (y0f + 1.f >= 0.f && y0f + 1.f <= 63.f) ? 1.f : 0.f;
    float vx0 = (x0f >= 0.f && x0f <= 63.f) ? 1.f : 0.f;
    float vx1 = (x0f + 1.f >= 0.f && x0f + 1.f <= 63.f) ? 1.f : 0.f;

    int yc0 = (int)fminf(fmaxf(y0f, 0.f), 63.f);
    int yc1 = (int)fminf(fmaxf(y0f + 1.f, 0.f), 63.f);
    int xc0 = (int)fminf(fmaxf(x0f, 0.f), 63.f);
    int xc1 = (int)fminf(fmaxf(x0f + 1.f, 0.f), 63.f);

    float w00 = (1 - wy) * (1 - wx) * vy0 * vx0 * mask;
    float w01 = (1 - wy) * wx       * vy0 * vx1 * mask;
    float w10 = wy       * (1 - wx) * vy1 * vx0 * mask;
    float w11 = wy       * wx       * vy1 * vx1 * mask;

    int plane = (b << 12);
    const float4* p00 = (const float4*)(g_coarse_up + ((plane + (yc0 << 6) + xc0) * CC) + g * CG);
    const float4* p01 = (const float4*)(g_coarse_up + ((plane + (yc0 << 6) + xc1) * CC) + g * CG);
    const float4* p10 = (const float4*)(g_coarse_up + ((plane + (yc1 << 6) + xc0) * CC) + g * CG);
    const float4* p11 = (const float4*)(g_coarse_up + ((plane + (yc1 << 6) + xc1) * CC) + g * CG);

    float4* dst = (float4*)(g_sampled + (size_t)(m * 9 + k) * CC + g * CG);
#pragma unroll
    for (int i = 0; i < 8; i++) {
        float4 a = p00[i], bb = p01[i], c = p10[i], d = p11[i];
        float4 r;
        r.x = w00*a.x + w01*bb.x + w10*c.x + w11*d.x;
        r.y = w00*a.y + w01*bb.y + w10*c.y + w11*d.y;
        r.z = w00*a.z + w01*bb.z + w10*c.z + w11*d.z;
        r.w = w00*a.w + w01*bb.w + w10*c.w + w11*d.w;
        dst[i] = r;
    }
}

// ---------------- launch --------------------------------------------------------
extern "C" void kernel_launch(void* const* d_in, const int* in_sizes, int n_in,
                              void* d_out, int out_size) {
    const float* coarse = (const float*)d_in[0];
    const float* fine   = (const float*)d_in[1];
    const float* w_att  = (const float*)d_in[2];
    const float* w_sel  = (const float*)d_in[3];
    const float* w_off  = (const float*)d_in[4];
    const float* w_om   = (const float*)d_in[5];
    const float* b_om   = (const float*)d_in[6];
    const float* w_dcn  = (const float*)d_in[7];
    const float* b_dcn  = (const float*)d_in[8];
    float* out = (float*)d_out;

    float *cu, *fcal, *alg, *om, *samp, *attn;
    cudaGetSymbolAddress((void**)&cu,   g_coarse_up);
    cudaGetSymbolAddress((void**)&fcal, g_fine_cal);
    cudaGetSymbolAddress((void**)&alg,  g_align);
    cudaGetSymbolAddress((void**)&om,   g_om);
    cudaGetSymbolAddress((void**)&samp, g_sampled);
    cudaGetSymbolAddress((void**)&attn, g_attn_p1);

    upsample_kernel<<<(BB*HH*WW*CC/4 + 255)/256, 256>>>(coarse);
    pool_part_kernel<<<64, 256>>>(fine);
    attn_kernel<<<BB, 256>>>(w_att);

    // fine_cal = (fine * (attn+1)) @ w_sel
    gemm_kernel<1,0><<<dim3(2,128), 256>>>(nullptr, w_sel, fcal,
        MTOT, CC, CC, fine, attn, nullptr, nullptr);

    // align = concat(fine_cal, 2*coarse_up) @ w_off
    gemm_kernel<2,0><<<dim3(4,128), 256>>>(nullptr, w_off, alg,
        MTOT, CF2, CF2, fcal, cu, nullptr, nullptr);

    // om = conv3x3(align, w_om) + b_om   (im2col-fused)
    gemm_kernel<3,1><<<dim3(2,128), 256>>>(nullptr, w_om, om,
        MTOT, NOM, KIM, alg, nullptr, b_om, nullptr);

    // deformable sampling -> g_sampled [16384, 9*256]
    sample_kernel<<<(MTOT*9*GRP + 255)/256, 256>>>();

    // out = relu(sampled @ w_dcn + b_dcn) + fine_cal
    gemm_kernel<0,2><<<dim3(2,128), 256>>>(samp, w_dcn, out,
        MTOT, CC, KDCN, nullptr, nullptr, b_dcn, fcal);
}

// round 13
// speedup vs baseline: 1.6998x; 1.6998x over previous
#include <cuda_runtime.h>
#include <cuda_bf16.h>
#include <math.h>
#include <stdint.h>

// Problem constants
#define BB   4
#define HH   64
#define WW   64
#define MTOT (BB*HH*WW)      // 16384 pixels
#define CC   256
#define CF2  512
#define NOM  216             // G*3*K
#define GRP  8
#define CG   32

// ---------------- scratch ----------------------------------------------------
__device__ float g_coarse_up[MTOT*CC];
__device__ float g_pool_part[64*CC];
__device__ float g_attn_p1[BB*CC];
__device__ float g_fine_cal[MTOT*CC];
__device__ float g_align[MTOT*CF2];
__device__ float g_om[MTOT*NOM];
__device__ __nv_bfloat16 g_align2[(size_t)MTOT*1024];       // split-bf16 align
__device__ __nv_bfloat16 g_samp2[(size_t)MTOT*4608];        // split-bf16 sampled
__device__ __nv_bfloat16 g_wom2[(size_t)256*9216];          // split-bf16 w_om^T (N padded to 256)
__device__ __nv_bfloat16 g_wdcn2[(size_t)256*4608];         // split-bf16 w_dcn^T

// ---------------- bilinear upsample ------------------------------------------
__global__ void upsample_kernel(const float* __restrict__ coarse) {
    int idx = blockIdx.x * blockDim.x + threadIdx.x;
    if (idx >= BB*HH*WW*(CC/4)) return;
    int c4 = idx & 63, x = (idx >> 6) & 63, y = (idx >> 12) & 63, b = idx >> 18;
    float syf = y * 0.5f - 0.25f, sxf = x * 0.5f - 0.25f;
    float y0f = floorf(syf), x0f = floorf(sxf);
    float wy = syf - y0f, wx = sxf - x0f;
    int y0 = max(0, min(31, (int)y0f)), y1 = max(0, min(31, (int)y0f + 1));
    int x0 = max(0, min(31, (int)x0f)), x1 = max(0, min(31, (int)x0f + 1));
    const float4* src = (const float4*)coarse;
    int base = b * 32 * 32 * 64;
    float4 v00 = src[base + (y0*32+x0)*64 + c4], v01 = src[base + (y0*32+x1)*64 + c4];
    float4 v10 = src[base + (y1*32+x0)*64 + c4], v11 = src[base + (y1*32+x1)*64 + c4];
    float4 r;
    r.x = (v00.x*(1-wx)+v01.x*wx)*(1-wy) + (v10.x*(1-wx)+v11.x*wx)*wy;
    r.y = (v00.y*(1-wx)+v01.y*wx)*(1-wy) + (v10.y*(1-wx)+v11.y*wx)*wy;
    r.z = (v00.z*(1-wx)+v01.z*wx)*(1-wy) + (v10.z*(1-wx)+v11.z*wx)*wy;
    r.w = (v00.w*(1-wx)+v01.w*wx)*(1-wy) + (v10.w*(1-wx)+v11.w*wx)*wy;
    ((float4*)g_coarse_up)[((b*64 + y)*64 + x)*64 + c4] = r;
}

// ---------------- pool + attention -------------------------------------------
__global__ void pool_part_kernel(const float* __restrict__ fine) {
    int bx = blockIdx.x, b = bx >> 4, t = bx & 15, c = threadIdx.x;
    float acc = 0.f;
    const float* p = fine + ((size_t)(b << 12) + t * 256) * CC + c;
    for (int s = 0; s < 256; s++) acc += p[(size_t)s * CC];
    g_pool_part[bx * CC + c] = acc;
}
__global__ void attn_kernel(const float* __restrict__ w_att) {
    __shared__ float ps[CC];
    int b = blockIdx.x, c = threadIdx.x;
    float acc = 0.f;
    for (int t = 0; t < 16; t++) acc += g_pool_part[(b * 16 + t) * CC + c];
    ps[c] = acc * (1.0f / 4096.0f);
    __syncthreads();
    float logit = 0.f;
    for (int k = 0; k < CC; k++) logit = fmaf(ps[k], w_att[k * CC + c], logit);
    g_attn_p1[b * CC + c] = 1.0f + 1.0f / (1.0f + expf(-logit));
}

// ---------------- scalar SGEMM (small stages) --------------------------------
#define Bb 128
#define Bn 128
#define Bk 16
template<int AMODE>
__device__ __forceinline__ float loadA(const float* __restrict__ aux0,
                                       const float* __restrict__ aux1, int m, int k) {
    if (AMODE == 1) return aux0[m * CC + k] * aux1[((m >> 12) << 8) + k];
    return (k < CC) ? aux0[m * CC + k] : 2.0f * aux1[m * CC + (k - CC)];
}
template<int AMODE>
__global__ void __launch_bounds__(256)
gemm_kernel(const float* __restrict__ B, float* __restrict__ C, int N, int K,
            const float* __restrict__ aux0, const float* __restrict__ aux1) {
    __shared__ float As[2][Bk][Bb + 4];
    __shared__ float Bs[2][Bk][Bn];
    int tid = threadIdx.x, tx = tid & 15, ty = tid >> 4;
    int m0 = blockIdx.y * Bb, n0 = blockIdx.x * Bn;
    float acc[8][8];
#pragma unroll
    for (int i = 0; i < 8; i++)
#pragma unroll
        for (int j = 0; j < 8; j++) acc[i][j] = 0.f;
    int a_kk = tid & 15, a_mrow = tid >> 4, b_nn = tid & 127, b_krow = tid >> 7;
    float pa[8], pb[8];
#pragma unroll
    for (int t = 0; t < 8; t++) pa[t] = loadA<AMODE>(aux0, aux1, m0 + a_mrow + t * 16, a_kk);
#pragma unroll
    for (int t = 0; t < 8; t++) pb[t] = B[(size_t)(b_krow + t * 2) * N + n0 + b_nn];
#pragma unroll
    for (int t = 0; t < 8; t++) As[0][a_kk][a_mrow + t * 16] = pa[t];
#pragma unroll
    for (int t = 0; t < 8; t++) Bs[0][b_krow + t * 2][b_nn] = pb[t];
    __syncthreads();
    int buf = 0;
    for (int k0 = 0; k0 < K; k0 += Bk, buf ^= 1) {
        bool has_next = (k0 + Bk) < K;
        if (has_next) {
            int kn = k0 + Bk;
#pragma unroll
            for (int t = 0; t < 8; t++) pa[t] = loadA<AMODE>(aux0, aux1, m0 + a_mrow + t * 16, kn + a_kk);
#pragma unroll
            for (int t = 0; t < 8; t++) pb[t] = B[(size_t)(kn + b_krow + t * 2) * N + n0 + b_nn];
        }
        float rA[2][8], rB[2][8];
        {
            float4 a0 = *(const float4*)&As[buf][0][ty*8], a1 = *(const float4*)&As[buf][0][ty*8+4];
            float4 b0 = *(const float4*)&Bs[buf][0][tx*8], b1 = *(const float4*)&Bs[buf][0][tx*8+4];
            rA[0][0]=a0.x;rA[0][1]=a0.y;rA[0][2]=a0.z;rA[0][3]=a0.w;rA[0][4]=a1.x;rA[0][5]=a1.y;rA[0][6]=a1.z;rA[0][7]=a1.w;
            rB[0][0]=b0.x;rB[0][1]=b0.y;rB[0][2]=b0.z;rB[0][3]=b0.w;rB[0][4]=b1.x;rB[0][5]=b1.y;rB[0][6]=b1.z;rB[0][7]=b1.w;
        }
#pragma unroll
        for (int kk = 0; kk < Bk; kk++) {
            int cur = kk & 1, nxt = cur ^ 1;
            if (kk < Bk - 1) {
                float4 a0 = *(const float4*)&As[buf][kk+1][ty*8], a1 = *(const float4*)&As[buf][kk+1][ty*8+4];
                float4 b0 = *(const float4*)&Bs[buf][kk+1][tx*8], b1 = *(const float4*)&Bs[buf][kk+1][tx*8+4];
                rA[nxt][0]=a0.x;rA[nxt][1]=a0.y;rA[nxt][2]=a0.z;rA[nxt][3]=a0.w;rA[nxt][4]=a1.x;rA[nxt][5]=a1.y;rA[nxt][6]=a1.z;rA[nxt][7]=a1.w;
                rB[nxt][0]=b0.x;rB[nxt][1]=b0.y;rB[nxt][2]=b0.z;rB[nxt][3]=b0.w;rB[nxt][4]=b1.x;rB[nxt][5]=b1.y;rB[nxt][6]=b1.z;rB[nxt][7]=b1.w;
            }
#pragma unroll
            for (int i = 0; i < 8; i++)
#pragma unroll
                for (int j = 0; j < 8; j++)
                    acc[i][j] = fmaf(rA[cur][i], rB[cur][j], acc[i][j]);
        }
        if (has_next) {
#pragma unroll
            for (int t = 0; t < 8; t++) As[buf^1][a_kk][a_mrow + t * 16] = pa[t];
#pragma unroll
            for (int t = 0; t < 8; t++) Bs[buf^1][b_krow + t * 2][b_nn] = pb[t];
            __syncthreads();
        }
    }
#pragma unroll
    for (int i = 0; i < 8; i++) {
        int m = m0 + ty * 8 + i;
#pragma unroll
        for (int j = 0; j < 8; j++)
            C[(size_t)m * N + n0 + tx * 8 + j] = acc[i][j];
    }
}

// ---------------- fp32 -> split bf16 conversions -----------------------------
__device__ __forceinline__ __nv_bfloat162 split_bf16(float v) {
    __nv_bfloat16 hi = __float2bfloat16(v);
    __nv_bfloat16 lo = __float2bfloat16(v - __bfloat162float(hi));
    __nv_bfloat162 p; p.x = hi; p.y = lo; return p;
}
// weights [K][Nsrc] f32 -> [256][2K] bf16 (transposed, N zero-padded)
__global__ void conv_w_kernel(const float* __restrict__ w, __nv_bfloat16* __restrict__ out,
                              int K, int Nsrc) {
    int id = blockIdx.x * 256 + threadIdx.x;
    if (id >= 256 * K) return;
    int n = id / K, k = id - n * K;
    float v = (n < Nsrc) ? w[(size_t)k * Nsrc + n] : 0.f;
    *(__nv_bfloat162*)(out + (size_t)n * 2 * K + 2 * k) = split_bf16(v);
}
// g_align [M][512] f32 -> g_align2 [M][1024] bf16
__global__ void conv_align_kernel() {
    int id = blockIdx.x * 256 + threadIdx.x;
    if (id >= MTOT * 512) return;
    ((__nv_bfloat162*)g_align2)[id] = split_bf16(g_align[id]);
}

// ---------------- deformable sampling (writes split bf16) --------------------
__global__ void sample_kernel() {
    int idx = blockIdx.x * blockDim.x + threadIdx.x;
    if (idx >= MTOT * 9 * GRP) return;
    int g = idx & 7, mk = idx >> 3, k = mk % 9, m = mk / 9;
    int b = m >> 12, y = (m >> 6) & 63, x = m & 63;
    const float* omp = g_om + (size_t)m * NOM;
    float dy = omp[g*18 + k*2], dx = omp[g*18 + k*2 + 1];
    float mask = 1.0f / (1.0f + expf(-omp[144 + g*9 + k]));
    float sy = (float)y + (float)(k/3 - 1) + dy;
    float sx = (float)x + (float)(k%3 - 1) + dx;
    float y0f = floorf(sy), x0f = floorf(sx);
    float wy = sy - y0f, wx = sx - x0f;
    float vy0 = (y0f >= 0.f && y0f <= 63.f) ? 1.f : 0.f;
    float vy1 = (y0f+1.f >= 0.f && y0f+1.f <= 63.f) ? 1.f : 0.f;
    float vx0 = (x0f >= 0.f && x0f <= 63.f) ? 1.f : 0.f;
    float vx1 = (x0f+1.f >= 0.f && x0f+1.f <= 63.f) ? 1.f : 0.f;
    int yc0 = (int)fminf(fmaxf(y0f, 0.f), 63.f), yc1 = (int)fminf(fmaxf(y0f+1.f, 0.f), 63.f);
    int xc0 = (int)fminf(fmaxf(x0f, 0.f), 63.f), xc1 = (int)fminf(fmaxf(x0f+1.f, 0.f), 63.f);
    float w00 = (1-wy)*(1-wx)*vy0*vx0*mask, w01 = (1-wy)*wx*vy0*vx1*mask;
    float w10 = wy*(1-wx)*vy1*vx0*mask,     w11 = wy*wx*vy1*vx1*mask;
    int plane = b << 12;
    const float4* p00 = (const float4*)(g_coarse_up + (plane + (yc0<<6) + xc0)*CC + g*CG);
    const float4* p01 = (const float4*)(g_coarse_up + (plane + (yc0<<6) + xc1)*CC + g*CG);
    const float4* p10 = (const float4*)(g_coarse_up + (plane + (yc1<<6) + xc0)*CC + g*CG);
    const float4* p11 = (const float4*)(g_coarse_up + (plane + (yc1<<6) + xc1)*CC + g*CG);
    __nv_bfloat162* dst = (__nv_bfloat162*)g_samp2 + (size_t)m*2304 + k*256 + g*CG;
#pragma unroll
    for (int i = 0; i < 8; i++) {
        float4 a = p00[i], bq = p01[i], c = p10[i], d = p11[i];
        __nv_bfloat162 o0 = split_bf16(w00*a.x + w01*bq.x + w10*c.x + w11*d.x);
        __nv_bfloat162 o1 = split_bf16(w00*a.y + w01*bq.y + w10*c.y + w11*d.y);
        __nv_bfloat162 o2 = split_bf16(w00*a.z + w01*bq.z + w10*c.z + w11*d.z);
        __nv_bfloat162 o3 = split_bf16(w00*a.w + w01*bq.w + w10*c.w + w11*d.w);
        uint4 pk;
        pk.x = *(uint32_t*)&o0; pk.y = *(uint32_t*)&o1; pk.z = *(uint32_t*)&o2; pk.w = *(uint32_t*)&o3;
        *(uint4*)(dst + i*4) = pk;
    }
}

// ---------------- HMMA (mma.sync) split-bf16 GEMM -----------------------------
// C[M x Nout] = A[M x K2] * B^T, B stored [256][K2] row-major (n-major).
// AM: 0 = plain A (g_samp2); 3 = im2col over g_align2 [B,H,W,1024]
// EP: 1 = +bias; 2 = relu(+bias)+add
// CTA 128x128 tile, 8 warps in 2x4, warp tile 64x32, mma.m16n8k16 bf16.
#define TPAD 72   // smem row stride (bf16): 144B = 36 banks -> conflict-free frags

__device__ __forceinline__ void mma16816(float* c, const uint32_t* a, const uint32_t* b) {
    asm volatile("mma.sync.aligned.m16n8k16.row.col.f32.bf16.bf16.f32 "
                 "{%0,%1,%2,%3}, {%4,%5,%6,%7}, {%8,%9}, {%0,%1,%2,%3};"
                 : "+f"(c[0]), "+f"(c[1]), "+f"(c[2]), "+f"(c[3])
                 : "r"(a[0]), "r"(a[1]), "r"(a[2]), "r"(a[3]), "r"(b[0]), "r"(b[1]));
}

template<int AM, int EP>
__global__ void __launch_bounds__(256)
tgemm_kernel(const __nv_bfloat16* __restrict__ Abf, const __nv_bfloat16* __restrict__ Bbf,
             float* __restrict__ C, const float* __restrict__ bias,
             const float* __restrict__ add, int K2, int Nout) {
    __shared__ __align__(16) __nv_bfloat16 As[128][TPAD];
    __shared__ __align__(16) __nv_bfloat16 Bs[128][TPAD];
    int tid = threadIdx.x, wid = tid >> 5, lane = tid & 31;
    int m0 = blockIdx.y * 128, n0 = blockIdx.x * 128;
    int mw = (wid >> 2) * 64;      // warp row offset in tile
    int nw = (wid & 3) * 32;       // warp col offset in tile

    float acc[4][4][4];
#pragma unroll
    for (int mt = 0; mt < 4; mt++)
#pragma unroll
        for (int nt = 0; nt < 4; nt++)
#pragma unroll
            for (int r = 0; r < 4; r++) acc[mt][nt][r] = 0.f;

    int nchunks = K2 >> 6;         // 64 bf16 per chunk
    for (int ch = 0; ch < nchunks; ch++) {
        // ---- load A tile: 128 rows x 64 bf16 = 1024 uint4 ----
#pragma unroll
        for (int i = 0; i < 4; i++) {
            int id = tid + i * 256;
            int row = id >> 3, c16 = id & 7;
            uint4 v = make_uint4(0, 0, 0, 0);
            if (AM == 0) {
                v = *(const uint4*)(Abf + (size_t)(m0 + row) * K2 + ch * 64 + c16 * 8);
            } else {
                int m = m0 + row;
                int b = m >> 12, y = (m >> 6) & 63, x = m & 63;
                int tap = ch >> 4, ky = tap / 3 - 1, kx = tap % 3 - 1;
                int yy = y + ky, xx = x + kx;
                if ((unsigned)yy < 64u && (unsigned)xx < 64u)
                    v = *(const uint4*)(Abf + (size_t)((((b << 6) + yy) << 6) + xx) * 1024
                                        + (ch & 15) * 64 + c16 * 8);
            }
            *(uint4*)&As[row][c16 * 8] = v;
        }
        // ---- load B tile: 128 rows (n) x 64 bf16 ----
#pragma unroll
        for (int i = 0; i < 4; i++) {
            int id = tid + i * 256;
            int row = id >> 3, c16 = id & 7;
            uint4 v = *(const uint4*)(Bbf + (size_t)(n0 + row) * K2 + ch * 64 + c16 * 8);
            *(uint4*)&Bs[row][c16 * 8] = v;
        }
        __syncthreads();

        // ---- 4 k16-steps of mma ----
#pragma unroll
        for (int ks = 0; ks < 4; ks++) {
            int k = ks * 16;
            uint32_t af[4][4], bf[4][2];
#pragma unroll
            for (int mt = 0; mt < 4; mt++) {
                int r = mw + mt * 16 + (lane >> 2);
                int kc = k + (lane & 3) * 2;
                af[mt][0] = *(const uint32_t*)&As[r][kc];
                af[mt][1] = *(const uint32_t*)&As[r + 8][kc];
                af[mt][2] = *(const uint32_t*)&As[r][kc + 8];
                af[mt][3] = *(const uint32_t*)&As[r + 8][kc + 8];
            }
#pragma unroll
            for (int nt = 0; nt < 4; nt++) {
                int cn = nw + nt * 8 + (lane >> 2);
                int kc = k + (lane & 3) * 2;
                bf[nt][0] = *(const uint32_t*)&Bs[cn][kc];
                bf[nt][1] = *(const uint32_t*)&Bs[cn][kc + 8];
            }
#pragma unroll
            for (int mt = 0; mt < 4; mt++)
#pragma unroll
                for (int nt = 0; nt < 4; nt++)
                    mma16816(acc[mt][nt], af[mt], bf[nt]);
        }
        __syncthreads();
    }

    // ---- epilogue ----
#pragma unroll
    for (int mt = 0; mt < 4; mt++) {
        int r0 = m0 + mw + mt * 16 + (lane >> 2);
#pragma unroll
        for (int nt = 0; nt < 4; nt++) {
            int c0 = n0 + nw + nt * 8 + (lane & 3) * 2;
#pragma unroll
            for (int h = 0; h < 2; h++) {       // row, row+8
                int m = r0 + h * 8;
#pragma unroll
                for (int j = 0; j < 2; j++) {   // col, col+1
                    int n = c0 + j;
                    if (n < Nout) {
                        float v = acc[mt][nt][h * 2 + j];
                        if (EP == 1) C[(size_t)m * Nout + n] = v + bias[n];
                        else C[(size_t)m * Nout + n] =
                            fmaxf(v + bias[n], 0.f) + add[(size_t)m * Nout + n];
                    }
                }
            }
        }
    }
}

// ---------------- launch ------------------------------------------------------
extern "C" void kernel_launch(void* const* d_in, const int* in_sizes, int n_in,
                              void* d_out, int out_size) {
    const float* coarse = (const float*)d_in[0];
    const float* fine   = (const float*)d_in[1];
    const float* w_att  = (const float*)d_in[2];
    const float* w_sel  = (const float*)d_in[3];
    const float* w_off  = (const float*)d_in[4];
    const float* w_om   = (const float*)d_in[5];
    const float* b_om   = (const float*)d_in[6];
    const float* w_dcn  = (const float*)d_in[7];
    const float* b_dcn  = (const float*)d_in[8];
    float* out = (float*)d_out;

    float *cu, *fcal, *alg, *om, *attn;
    __nv_bfloat16 *al2, *sp2, *wom2, *wdcn2;
    cudaGetSymbolAddress((void**)&cu,    g_coarse_up);
    cudaGetSymbolAddress((void**)&fcal,  g_fine_cal);
    cudaGetSymbolAddress((void**)&alg,   g_align);
    cudaGetSymbolAddress((void**)&om,    g_om);
    cudaGetSymbolAddress((void**)&attn,  g_attn_p1);
    cudaGetSymbolAddress((void**)&al2,   g_align2);
    cudaGetSymbolAddress((void**)&sp2,   g_samp2);
    cudaGetSymbolAddress((void**)&wom2,  g_wom2);
    cudaGetSymbolAddress((void**)&wdcn2, g_wdcn2);

    upsample_kernel<<<(BB*HH*WW*CC/4 + 255)/256, 256>>>(coarse);
    pool_part_kernel<<<64, 256>>>(fine);
    attn_kernel<<<BB, 256>>>(w_att);

    // fine_cal = (fine * (attn+1)) @ w_sel          [scalar]
    gemm_kernel<1><<<dim3(2,128), 256>>>(w_sel, fcal, CC, CC, fine, attn);
    // align = concat(fine_cal, 2*coarse_up) @ w_off [scalar]
    gemm_kernel<2><<<dim3(4,128), 256>>>(w_off, alg, CF2, CF2, fcal, cu);

    // split-bf16 conversions
    conv_align_kernel<<<(MTOT*512 + 255)/256, 256>>>();
    conv_w_kernel<<<(256*4608 + 255)/256, 256>>>(w_om, wom2, 4608, NOM);
    conv_w_kernel<<<(256*2304 + 255)/256, 256>>>(w_dcn, wdcn2, 2304, 256);

    // om = conv3x3(align, w_om) + b_om   [HMMA, im2col-fused, K2 = 2*4608]
    tgemm_kernel<3,1><<<dim3(2,128), 256>>>(al2, wom2, om, b_om, nullptr, 9216, NOM);

    // deformable sampling -> g_samp2 (split bf16)
    sample_kernel<<<(MTOT*9*GRP + 255)/256, 256>>>();

    // out = relu(sampled @ w_dcn + b_dcn) + fine_cal  [HMMA, K2 = 2*2304]
    tgemm_kernel<0,2><<<dim3(2,128), 256>>>(sp2, wdcn2, out, b_dcn, fcal, 4608, 256);
}